// round 14
// baseline (speedup 1.0000x reference)
#include <cuda_runtime.h>
#include <cuda_bf16.h>
#include <cstdint>

#define NSTATE (1u << 23)

__device__ float g_scratch[1u << 24];
__device__ __nv_bfloat16 g_ubf[262144];   // 4 gates x 4 matrices x 16384 bf16

#define SMEM_BYTES_LO 163840u   // U image 128KB + 2 x 16KB state buffers
#define SMEM_BYTES_HI 196608u   // U-half 64KB + 2 x 64KB state buffers
#define SGN 0x80008000u

#define AL_OFF 131072u          // gates 0-2 state buffers
#define BH_OFF 65536u           // gate 3 state buffers

__device__ __forceinline__ uint32_t smem_u32(const void* p) {
    uint32_t a;
    asm("{ .reg .u64 t; cvta.to.shared.u64 t, %1; cvt.u32.u64 %0, t; }" : "=r"(a) : "l"(p));
    return a;
}

#define CPASYNC16(saddr, gptr)                                                  \
    asm volatile("cp.async.cg.shared.global [%0], [%1], 16;"                    \
        :: "r"(saddr), "l"(gptr) : "memory")

#define LDM4(r, addr)                                                           \
    asm volatile("ldmatrix.sync.aligned.m8n8.x4.shared.b16 {%0,%1,%2,%3}, [%4];"\
        : "=r"((r)[0]), "=r"((r)[1]), "=r"((r)[2]), "=r"((r)[3]) : "r"(addr))

#define LDM4T(r, addr)                                                          \
    asm volatile("ldmatrix.sync.aligned.m8n8.x4.trans.shared.b16 {%0,%1,%2,%3}, [%4];"\
        : "=r"((r)[0]), "=r"((r)[1]), "=r"((r)[2]), "=r"((r)[3]) : "r"(addr))

#define MMA(C, A, b0v, b1v)                                                     \
    asm volatile("mma.sync.aligned.m16n8k16.row.col.f32.bf16.bf16.f32 "         \
        "{%0,%1,%2,%3}, {%4,%5,%6,%7}, {%8,%9}, {%0,%1,%2,%3};"                 \
        : "+f"((C)[0]), "+f"((C)[1]), "+f"((C)[2]), "+f"((C)[3])                \
        : "r"((A)[0]), "r"((A)[1]), "r"((A)[2]), "r"((A)[3]), "r"(b0v), "r"(b1v))

// A-side negation variant (gates 0-2, state=A, U=B register-resident):
// ch1 = A_r*B_r - A_i*B_i ; ch0 = A_i*B_r + A_r*B_i (hi*hi + hi*lo + lo*hi)
#define MMA12P(ACC0, ACC1, AF, N2, N3, BF, J2)                                  \
    MMA(ACC1, AF[0], BF[0][J2], BF[0][(J2) + 2]);                               \
    MMA(ACC1, AF[0], BF[1][J2], BF[1][(J2) + 2]);                               \
    MMA(ACC1, AF[1], BF[0][J2], BF[0][(J2) + 2]);                               \
    MMA(ACC1, N2,    BF[2][J2], BF[2][(J2) + 2]);                               \
    MMA(ACC1, N2,    BF[3][J2], BF[3][(J2) + 2]);                               \
    MMA(ACC1, N3,    BF[2][J2], BF[2][(J2) + 2]);                               \
    MMA(ACC0, AF[2], BF[0][J2], BF[0][(J2) + 2]);                               \
    MMA(ACC0, AF[2], BF[1][J2], BF[1][(J2) + 2]);                               \
    MMA(ACC0, AF[3], BF[0][J2], BF[0][(J2) + 2]);                               \
    MMA(ACC0, AF[0], BF[2][J2], BF[2][(J2) + 2]);                               \
    MMA(ACC0, AF[0], BF[3][J2], BF[3][(J2) + 2]);                               \
    MMA(ACC0, AF[1], BF[2][J2], BF[2][(J2) + 2]);

// B-side negation variant (gate 3, U=A register-resident, state=B):
// ch1 = A_r*B_r - A_i*B_i ; ch0 = A_r*B_i + A_i*B_r
#define MMA12B(ACC0, ACC1, AF, BF, NB2, NB3, J2)                                \
    MMA(ACC1, AF[0], BF[0][J2], BF[0][(J2) + 2]);                               \
    MMA(ACC1, AF[0], BF[1][J2], BF[1][(J2) + 2]);                               \
    MMA(ACC1, AF[1], BF[0][J2], BF[0][(J2) + 2]);                               \
    MMA(ACC1, AF[2], NB2[J2],   NB2[(J2) + 2]);                                 \
    MMA(ACC1, AF[2], NB3[J2],   NB3[(J2) + 2]);                                 \
    MMA(ACC1, AF[3], NB2[J2],   NB2[(J2) + 2]);                                 \
    MMA(ACC0, AF[0], BF[2][J2], BF[2][(J2) + 2]);                               \
    MMA(ACC0, AF[0], BF[3][J2], BF[3][(J2) + 2]);                               \
    MMA(ACC0, AF[1], BF[2][J2], BF[2][(J2) + 2]);                               \
    MMA(ACC0, AF[2], BF[0][J2], BF[0][(J2) + 2]);                               \
    MMA(ACC0, AF[2], BF[1][J2], BF[1][(J2) + 2]);                               \
    MMA(ACC0, AF[3], BF[0][J2], BF[0][(J2) + 2]);

// fp32 x8 -> bf16 hi (16B) + bf16 lo (16B)
__device__ __forceinline__ void cvt8(float4 x, float4 y, uint4* hi, uint4* lo) {
    float f[8] = {x.x, x.y, x.z, x.w, y.x, y.y, y.z, y.w};
    uint32_t h[8], l[8];
    #pragma unroll
    for (int i = 0; i < 8; ++i) {
        __nv_bfloat16 hb = __float2bfloat16(f[i]);
        h[i] = (uint32_t)__bfloat16_as_ushort(hb);
        l[i] = (uint32_t)__bfloat16_as_ushort(__float2bfloat16(f[i] - __bfloat162float(hb)));
    }
    *hi = make_uint4(h[0] | (h[1] << 16), h[2] | (h[3] << 16),
                     h[4] | (h[5] << 16), h[6] | (h[7] << 16));
    *lo = make_uint4(l[0] | (l[1] << 16), l[2] | (l[3] << 16),
                     l[4] | (l[5] << 16), l[6] | (l[7] << 16));
}

// ---------------------------------------------------------------------------
__global__ void prep_u(const float* __restrict__ U)
{
    const int i = blockIdx.x * 256 + threadIdx.x;   // 131072
    const int a = i & 127, k = (i >> 7) & 127, c = (i >> 14) & 1, g = i >> 15;
    const float x = U[i];
    const __nv_bfloat16 hi = __float2bfloat16(x);
    const __nv_bfloat16 lo = __float2bfloat16(x - __bfloat162float(hi));
    const int h = k * 128 + (((a >> 3) ^ (k & 7)) << 3) + (a & 7);
    g_ubf[g * 65536 + (c * 2 + 0) * 16384 + h] = hi;
    g_ubf[g * 65536 + (c * 2 + 1) * 16384 + h] = lo;
}

// ---------------------------------------------------------------------------
// Gates 0-2, REGISTER-RESIDENT U (R13, unchanged): 256 threads, 8 warps x 16 cols.
__global__ void __launch_bounds__(256, 1)
gate_lowr(const float* __restrict__ in, float* __restrict__ out,
          const __nv_bfloat16* __restrict__ img)
{
    extern __shared__ char smem[];
    const uint32_t sb = smem_u32(smem);
    const int t = threadIdx.x, lane = t & 31, w = t >> 5;

    {
        const uint4* src = (const uint4*)img;
        #pragma unroll
        for (int j = 0; j < 32; ++j) {
            const int idx = t + 256 * j;
            CPASYNC16(sb + (uint32_t)idx * 16u, src + idx);
        }
        asm volatile("cp.async.commit_group;" ::: "memory");
    }

    int item = blockIdx.x;
    {
        const size_t base = (size_t)item * 2048;
        #pragma unroll
        for (int s = 0; s < 2; ++s) {
            const int slot = t + 256 * s;
            const int c = slot & 15, r = (slot >> 4) & 15, ch = slot >> 8;
            const float4* p = (const float4*)(in + (size_t)ch * NSTATE + base + r * 128 + c * 8);
            uint4 hi, lo;
            cvt8(p[0], p[1], &hi, &lo);
            char* wp = smem + AL_OFF + (ch * 2) * 4096 + r * 256 + ((c ^ (r & 7)) * 16);
            *(uint4*)wp = hi;
            *(uint4*)(wp + 4096) = lo;
        }
    }
    asm volatile("cp.async.wait_group 0;" ::: "memory");
    __syncthreads();

    const int ncol0 = w * 16;
    const int ar = lane & 15, acl = lane >> 4, ar7 = ar & 7;
    const int brow = ncol0 + (lane & 15), bcl = lane >> 4;
    const uint32_t bbase = sb + (uint32_t)brow * 256u;
    const int br7 = brow & 7;
    const int rg = lane >> 2, tg = lane & 3;

    uint32_t uf[8][4][4];
    #pragma unroll
    for (int ks = 0; ks < 8; ++ks) {
        const uint32_t ba = bbase + (uint32_t)(((ks * 2 + bcl) ^ br7) << 4);
        LDM4(uf[ks][0], ba);
        LDM4(uf[ks][1], ba + 32768);
        LDM4(uf[ks][2], ba + 65536);
        LDM4(uf[ks][3], ba + 98304);
    }

    uint32_t buf = 0;
    for (; item < 4096; item += 148) {
        const int next = item + 148;
        const bool hasnext = next < 4096;
        float4 stg[4];
        if (hasnext) {
            const size_t base = (size_t)next * 2048;
            #pragma unroll
            for (int s = 0; s < 2; ++s) {
                const int slot = t + 256 * s;
                const int c = slot & 15, r = (slot >> 4) & 15, ch = slot >> 8;
                const float4* p = (const float4*)(in + (size_t)ch * NSTATE + base + r * 128 + c * 8);
                stg[2 * s] = p[0];
                stg[2 * s + 1] = p[1];
            }
        }

        float acc0[2][4], acc1[2][4];
        #pragma unroll
        for (int j = 0; j < 2; ++j)
            #pragma unroll
            for (int q = 0; q < 4; ++q) { acc0[j][q] = 0.f; acc1[j][q] = 0.f; }

        const uint32_t abase = sb + AL_OFF + buf * 16384u + (uint32_t)ar * 256u;
        #pragma unroll
        for (int ks = 0; ks < 8; ++ks) {
            uint32_t af[4][4], naf2[4], naf3[4];
            const uint32_t aa = abase + (uint32_t)(((ks * 2 + acl) ^ ar7) << 4);
            LDM4(af[0], aa);
            LDM4(af[1], aa + 4096);
            LDM4(af[2], aa + 8192);
            LDM4(af[3], aa + 12288);
            #pragma unroll
            for (int q = 0; q < 4; ++q) { naf2[q] = af[2][q] ^ SGN; naf3[q] = af[3][q] ^ SGN; }

            MMA12P(acc0[0], acc1[0], af, naf2, naf3, uf[ks], 0)
            MMA12P(acc0[1], acc1[1], af, naf2, naf3, uf[ks], 1)
        }

        if (hasnext) {
            #pragma unroll
            for (int s = 0; s < 2; ++s) {
                const int slot = t + 256 * s;
                const int c = slot & 15, r = (slot >> 4) & 15, ch = slot >> 8;
                uint4 hi, lo;
                cvt8(stg[2 * s], stg[2 * s + 1], &hi, &lo);
                char* wp = smem + AL_OFF + (buf ^ 1u) * 16384u + (ch * 2) * 4096 + r * 256
                         + ((c ^ (r & 7)) * 16);
                *(uint4*)wp = hi;
                *(uint4*)(wp + 4096) = lo;
            }
        }

        {
            const size_t row0 = (size_t)item * 16 + rg;
            float* o0 = out;
            float* o1 = out + NSTATE;
            #pragma unroll
            for (int j = 0; j < 2; ++j) {
                const int n = ncol0 + j * 8 + tg * 2;
                *(float2*)(o0 + row0 * 128 + n)       = make_float2(acc0[j][0], acc0[j][1]);
                *(float2*)(o0 + (row0 + 8) * 128 + n) = make_float2(acc0[j][2], acc0[j][3]);
                *(float2*)(o1 + row0 * 128 + n)       = make_float2(acc1[j][0], acc1[j][1]);
                *(float2*)(o1 + (row0 + 8) * 128 + n) = make_float2(acc1[j][2], acc1[j][3]);
            }
        }
        __syncthreads();
        buf ^= 1u;
    }
}

// ---------------------------------------------------------------------------
// Gate 3, REGISTER-RESIDENT U: 256 threads, 8 warps x (16 k-rows x 32 l-cols).
// U (A operand) fragments loaded once (128 regs); mainloop issues only the
// B-side ldmatrix.trans (state), halving per-item crossbar traffic.
__global__ void __launch_bounds__(256, 1)
gate_highr(const float* __restrict__ in, float* __restrict__ out,
           const __nv_bfloat16* __restrict__ img)
{
    extern __shared__ char smem[];
    const uint32_t sb = smem_u32(smem);
    const int t = threadIdx.x, lane = t & 31, w = t >> 5;
    const int khalf = blockIdx.x & 1;
    const int pairid = blockIdx.x >> 1;   // 0..73

    // stage U k-half once (64KB, pre-swizzled; 64 rows per matrix)
    {
        const uint4* src = (const uint4*)img;
        #pragma unroll
        for (int j = 0; j < 16; ++j) {
            const int idx = t + 256 * j;              // 0..4095
            const int m = idx >> 10, within = idx & 1023;
            CPASYNC16(sb + (uint32_t)idx * 16u, src + m * 2048 + khalf * 1024 + within);
        }
        asm volatile("cp.async.commit_group;" ::: "memory");
    }

    int widx = pairid;                    // 1024 = 512 chunks x 2 l-halves
    // first item convert (2048 slots, 8 per thread)
    {
        const int chunk = widx >> 1, lh = widx & 1;
        const size_t cb = (size_t)chunk * 16384;
        #pragma unroll
        for (int s = 0; s < 8; ++s) {
            const int slot = t + 256 * s;
            const int c = slot & 7, a = (slot >> 3) & 127, ch = slot >> 10;
            const float4* p = (const float4*)(in + (size_t)ch * NSTATE + cb + a * 128 + lh * 64 + c * 8);
            uint4 hi, lo;
            cvt8(p[0], p[1], &hi, &lo);
            char* wp = smem + BH_OFF + (ch * 2) * 16384 + a * 128 + ((c ^ (a & 7)) * 16);
            *(uint4*)wp = hi;
            *(uint4*)(wp + 16384) = lo;
        }
    }
    asm volatile("cp.async.wait_group 0;" ::: "memory");
    __syncthreads();

    const int mrow0 = (w & 3) * 16, ncol0 = (w >> 2) * 32;
    const int ar = mrow0 + (lane & 15), acl = lane >> 4, ar7 = ar & 7;
    const int br_off = (lane & 7) + ((lane & 16) >> 1), bcl = (lane >> 3) & 1;
    const int rg = lane >> 2, tg = lane & 3;

    // Load this warp's U (A-side) fragments ONCE (128 registers).
    uint32_t auf[8][4][4];
    {
        const uint32_t abase = sb + (uint32_t)ar * 256u;
        #pragma unroll
        for (int ks = 0; ks < 8; ++ks) {
            const uint32_t aa = abase + (uint32_t)(((ks * 2 + acl) ^ ar7) << 4);
            LDM4(auf[ks][0], aa);
            LDM4(auf[ks][1], aa + 16384);
            LDM4(auf[ks][2], aa + 32768);
            LDM4(auf[ks][3], aa + 49152);
        }
    }

    const int cidx0 = (ncol0 >> 3) + bcl;        // group 0 chunk index
    const int cidx1 = cidx0 + 2;                 // group 1 (+16 cols)

    uint32_t buf = 0;
    for (; widx < 1024; widx += 74) {
        const int chunk = widx >> 1, lh = widx & 1;
        const size_t cb = (size_t)chunk * 16384;
        const int nwidx = widx + 74;
        const bool hasnext = nwidx < 1024;
        const int nchunk = nwidx >> 1, nlh = nwidx & 1;
        const size_t ncb = (size_t)nchunk * 16384;

        float4 stg[4];                    // 2 slots staged; 6 loaded after MMA
        if (hasnext) {
            #pragma unroll
            for (int s = 0; s < 2; ++s) {
                const int slot = t + 256 * s;
                const int c = slot & 7, a = (slot >> 3) & 127, ch = slot >> 10;
                const float4* p = (const float4*)(in + (size_t)ch * NSTATE + ncb + a * 128 + nlh * 64 + c * 8);
                stg[2 * s] = p[0];
                stg[2 * s + 1] = p[1];
            }
        }

        float acc0[4][4], acc1[4][4];
        #pragma unroll
        for (int j = 0; j < 4; ++j)
            #pragma unroll
            for (int q = 0; q < 4; ++q) { acc0[j][q] = 0.f; acc1[j][q] = 0.f; }

        const uint32_t bbuf = sb + BH_OFF + buf * 65536u;
        #pragma unroll
        for (int ks = 0; ks < 8; ++ks) {
            const int row = ks * 16 + br_off;
            const uint32_t rb = bbuf + (uint32_t)row * 128u;
            const int r7 = row & 7;
            // group 0 (cols ncol0..+15)
            {
                uint32_t bf[4][4], nb2[4], nb3[4];
                const uint32_t ba = rb + (uint32_t)((cidx0 ^ r7) << 4);
                LDM4T(bf[0], ba);
                LDM4T(bf[1], ba + 16384);
                LDM4T(bf[2], ba + 32768);
                LDM4T(bf[3], ba + 49152);
                #pragma unroll
                for (int q = 0; q < 4; ++q) { nb2[q] = bf[2][q] ^ SGN; nb3[q] = bf[3][q] ^ SGN; }
                MMA12B(acc0[0], acc1[0], auf[ks], bf, nb2, nb3, 0)
                MMA12B(acc0[1], acc1[1], auf[ks], bf, nb2, nb3, 1)
            }
            // group 1 (cols ncol0+16..+31)
            {
                uint32_t bf[4][4], nb2[4], nb3[4];
                const uint32_t ba = rb + (uint32_t)((cidx1 ^ r7) << 4);
                LDM4T(bf[0], ba);
                LDM4T(bf[1], ba + 16384);
                LDM4T(bf[2], ba + 32768);
                LDM4T(bf[3], ba + 49152);
                #pragma unroll
                for (int q = 0; q < 4; ++q) { nb2[q] = bf[2][q] ^ SGN; nb3[q] = bf[3][q] ^ SGN; }
                MMA12B(acc0[2], acc1[2], auf[ks], bf, nb2, nb3, 0)
                MMA12B(acc0[3], acc1[3], auf[ks], bf, nb2, nb3, 1)
            }
        }

        if (hasnext) {
            #pragma unroll
            for (int s = 0; s < 2; ++s) {
                const int slot = t + 256 * s;
                const int c = slot & 7, a = (slot >> 3) & 127, ch = slot >> 10;
                uint4 hi, lo;
                cvt8(stg[2 * s], stg[2 * s + 1], &hi, &lo);
                char* wp = smem + BH_OFF + (buf ^ 1u) * 65536u + (ch * 2) * 16384 + a * 128
                         + ((c ^ (a & 7)) * 16);
                *(uint4*)wp = hi;
                *(uint4*)(wp + 16384) = lo;
            }
            #pragma unroll
            for (int s = 2; s < 8; ++s) {
                const int slot = t + 256 * s;
                const int c = slot & 7, a = (slot >> 3) & 127, ch = slot >> 10;
                const float4* p = (const float4*)(in + (size_t)ch * NSTATE + ncb + a * 128 + nlh * 64 + c * 8);
                uint4 hi, lo;
                cvt8(p[0], p[1], &hi, &lo);
                char* wp = smem + BH_OFF + (buf ^ 1u) * 65536u + (ch * 2) * 16384 + a * 128
                         + ((c ^ (a & 7)) * 16);
                *(uint4*)wp = hi;
                *(uint4*)(wp + 16384) = lo;
            }
        }

        {
            const size_t row0 = (size_t)khalf * 64 + mrow0 + rg;
            float* o0 = out + cb;
            float* o1 = out + NSTATE + cb;
            #pragma unroll
            for (int g = 0; g < 2; ++g)
                #pragma unroll
                for (int j2 = 0; j2 < 2; ++j2) {
                    const int j = g * 2 + j2;
                    const int n = lh * 64 + ncol0 + g * 16 + j2 * 8 + tg * 2;
                    *(float2*)(o0 + row0 * 128 + n)       = make_float2(acc0[j][0], acc0[j][1]);
                    *(float2*)(o0 + (row0 + 8) * 128 + n) = make_float2(acc0[j][2], acc0[j][3]);
                    *(float2*)(o1 + row0 * 128 + n)       = make_float2(acc1[j][0], acc1[j][1]);
                    *(float2*)(o1 + (row0 + 8) * 128 + n) = make_float2(acc1[j][2], acc1[j][3]);
                }
        }
        __syncthreads();
        buf ^= 1u;
    }
}

// ---------------------------------------------------------------------------
extern "C" void kernel_launch(void* const* d_in, const int* in_sizes, int n_in,
                              void* d_out, int out_size)
{
    const float* state = (const float*)d_in[0];
    const float* U     = (const float*)d_in[1];
    if (n_in >= 2 && in_sizes[0] < in_sizes[1]) {
        const float* tmp = state; state = U; U = tmp;
    }
    float* out = (float*)d_out;

    float* scratch = nullptr;
    cudaGetSymbolAddress((void**)&scratch, g_scratch);
    __nv_bfloat16* ubf = nullptr;
    cudaGetSymbolAddress((void**)&ubf, g_ubf);

    cudaFuncSetAttribute(gate_lowr,  cudaFuncAttributeMaxDynamicSharedMemorySize, (int)SMEM_BYTES_LO);
    cudaFuncSetAttribute(gate_highr, cudaFuncAttributeMaxDynamicSharedMemorySize, (int)SMEM_BYTES_HI);

    prep_u<<<512, 256>>>(U);
    gate_lowr<<<148, 256, SMEM_BYTES_LO>>>(state,   scratch, ubf);            // gate 0
    gate_lowr<<<148, 256, SMEM_BYTES_LO>>>(scratch, out,     ubf + 65536);    // gate 1
    gate_lowr<<<148, 256, SMEM_BYTES_LO>>>(out,     scratch, ubf + 131072);   // gate 2
    gate_highr<<<148, 256, SMEM_BYTES_HI>>>(scratch, out,    ubf + 196608);   // gate 3
}

// round 15
// speedup vs baseline: 1.1136x; 1.1136x over previous
#include <cuda_runtime.h>
#include <cuda_bf16.h>
#include <cstdint>

#define NSTATE (1u << 23)

__device__ float g_scratch[1u << 24];
__device__ __nv_bfloat16 g_ubf[262144];   // 4 gates x 4 matrices x 16384 bf16

#define SMEM_BYTES_LO 163840u   // U image 128KB + 2 x 16KB state buffers
#define SMEM_BYTES_HI 196608u   // U-half 64KB + 2 x 64KB state buffers
#define SGN 0x80008000u

#define AL_OFF 131072u          // gates 0-2 state buffers
#define BH_OFF 65536u           // gate 3 state buffers

__device__ __forceinline__ uint32_t smem_u32(const void* p) {
    uint32_t a;
    asm("{ .reg .u64 t; cvta.to.shared.u64 t, %1; cvt.u32.u64 %0, t; }" : "=r"(a) : "l"(p));
    return a;
}

#define CPASYNC16(saddr, gptr)                                                  \
    asm volatile("cp.async.cg.shared.global [%0], [%1], 16;"                    \
        :: "r"(saddr), "l"(gptr) : "memory")

#define LDM4(r, addr)                                                           \
    asm volatile("ldmatrix.sync.aligned.m8n8.x4.shared.b16 {%0,%1,%2,%3}, [%4];"\
        : "=r"((r)[0]), "=r"((r)[1]), "=r"((r)[2]), "=r"((r)[3]) : "r"(addr))

#define LDM4T(r, addr)                                                          \
    asm volatile("ldmatrix.sync.aligned.m8n8.x4.trans.shared.b16 {%0,%1,%2,%3}, [%4];"\
        : "=r"((r)[0]), "=r"((r)[1]), "=r"((r)[2]), "=r"((r)[3]) : "r"(addr))

#define MMA(C, A, b0v, b1v)                                                     \
    asm volatile("mma.sync.aligned.m16n8k16.row.col.f32.bf16.bf16.f32 "         \
        "{%0,%1,%2,%3}, {%4,%5,%6,%7}, {%8,%9}, {%0,%1,%2,%3};"                 \
        : "+f"((C)[0]), "+f"((C)[1]), "+f"((C)[2]), "+f"((C)[3])                \
        : "r"((A)[0]), "r"((A)[1]), "r"((A)[2]), "r"((A)[3]), "r"(b0v), "r"(b1v))

// 12-MMA on mixed reg/SMEM U operands:
// UH0=Ur_hi(reg) UH1=Ui_hi(reg), BL0=Ur_lo BL1=Ui_lo (fresh from SMEM)
// ch1 = Sr*Ur - Si*Ui ; ch0 = Si*Ur + Sr*Ui (hi*hi + hi*lo + lo*hi)
#define MMA12W(ACC0, ACC1, AF, N2, N3, UH0, UH1, BL0, BL1, J2)                  \
    MMA(ACC1, AF[0], UH0[J2], UH0[(J2) + 2]);                                   \
    MMA(ACC1, AF[0], BL0[J2], BL0[(J2) + 2]);                                   \
    MMA(ACC1, AF[1], UH0[J2], UH0[(J2) + 2]);                                   \
    MMA(ACC1, N2,    UH1[J2], UH1[(J2) + 2]);                                   \
    MMA(ACC1, N2,    BL1[J2], BL1[(J2) + 2]);                                   \
    MMA(ACC1, N3,    UH1[J2], UH1[(J2) + 2]);                                   \
    MMA(ACC0, AF[2], UH0[J2], UH0[(J2) + 2]);                                   \
    MMA(ACC0, AF[2], BL0[J2], BL0[(J2) + 2]);                                   \
    MMA(ACC0, AF[3], UH0[J2], UH0[(J2) + 2]);                                   \
    MMA(ACC0, AF[0], UH1[J2], UH1[(J2) + 2]);                                   \
    MMA(ACC0, AF[0], BL1[J2], BL1[(J2) + 2]);                                   \
    MMA(ACC0, AF[1], UH1[J2], UH1[(J2) + 2]);

// Full-SMEM variant (gate 3, unchanged R12)
#define MMA12P(ACC0, ACC1, AF, N2, N3, BF, J2)                                  \
    MMA(ACC1, AF[0], BF[0][J2], BF[0][(J2) + 2]);                               \
    MMA(ACC1, AF[0], BF[1][J2], BF[1][(J2) + 2]);                               \
    MMA(ACC1, AF[1], BF[0][J2], BF[0][(J2) + 2]);                               \
    MMA(ACC1, N2,    BF[2][J2], BF[2][(J2) + 2]);                               \
    MMA(ACC1, N2,    BF[3][J2], BF[3][(J2) + 2]);                               \
    MMA(ACC1, N3,    BF[2][J2], BF[2][(J2) + 2]);                               \
    MMA(ACC0, AF[2], BF[0][J2], BF[0][(J2) + 2]);                               \
    MMA(ACC0, AF[2], BF[1][J2], BF[1][(J2) + 2]);                               \
    MMA(ACC0, AF[3], BF[0][J2], BF[0][(J2) + 2]);                               \
    MMA(ACC0, AF[0], BF[2][J2], BF[2][(J2) + 2]);                               \
    MMA(ACC0, AF[0], BF[3][J2], BF[3][(J2) + 2]);                               \
    MMA(ACC0, AF[1], BF[2][J2], BF[2][(J2) + 2]);

// fp32 x8 -> bf16 hi (16B) + bf16 lo (16B)
__device__ __forceinline__ void cvt8(float4 x, float4 y, uint4* hi, uint4* lo) {
    float f[8] = {x.x, x.y, x.z, x.w, y.x, y.y, y.z, y.w};
    uint32_t h[8], l[8];
    #pragma unroll
    for (int i = 0; i < 8; ++i) {
        __nv_bfloat16 hb = __float2bfloat16(f[i]);
        h[i] = (uint32_t)__bfloat16_as_ushort(hb);
        l[i] = (uint32_t)__bfloat16_as_ushort(__float2bfloat16(f[i] - __bfloat162float(hb)));
    }
    *hi = make_uint4(h[0] | (h[1] << 16), h[2] | (h[3] << 16),
                     h[4] | (h[5] << 16), h[6] | (h[7] << 16));
    *lo = make_uint4(l[0] | (l[1] << 16), l[2] | (l[3] << 16),
                     l[4] | (l[5] << 16), l[6] | (l[7] << 16));
}

// ---------------------------------------------------------------------------
__global__ void prep_u(const float* __restrict__ U)
{
    const int i = blockIdx.x * 256 + threadIdx.x;   // 131072
    const int a = i & 127, k = (i >> 7) & 127, c = (i >> 14) & 1, g = i >> 15;
    const float x = U[i];
    const __nv_bfloat16 hi = __float2bfloat16(x);
    const __nv_bfloat16 lo = __float2bfloat16(x - __bfloat162float(hi));
    const int h = k * 128 + (((a >> 3) ^ (k & 7)) << 3) + (a & 7);
    g_ubf[g * 65536 + (c * 2 + 0) * 16384 + h] = hi;
    g_ubf[g * 65536 + (c * 2 + 1) * 16384 + h] = lo;
}

// ---------------------------------------------------------------------------
// Gates 0-2, WARP-SPECIALIZED: 384 threads.
// Warps 0-7: MMA consumers (16 cols each, U-hi mats register-resident).
// Warps 8-11: producers — all LDG + convert for the next item.
__global__ void __launch_bounds__(384, 1)
gate_lows(const float* __restrict__ in, float* __restrict__ out,
          const __nv_bfloat16* __restrict__ img)
{
    extern __shared__ char smem[];
    const uint32_t sb = smem_u32(smem);
    const int t = threadIdx.x, lane = t & 31, w = t >> 5;
    const bool mma_warp = (w < 8);

    // stage U image once (128KB, pre-swizzled)
    for (int idx = t; idx < 8192; idx += 384)
        CPASYNC16(sb + (uint32_t)idx * 16u, ((const uint4*)img) + idx);
    asm volatile("cp.async.commit_group;" ::: "memory");

    int item = blockIdx.x;
    // producers convert first item directly
    if (!mma_warp) {
        const int pt = t - 256;           // 0..127
        const size_t base = (size_t)item * 2048;
        #pragma unroll
        for (int s = 0; s < 4; ++s) {
            const int slot = pt + 128 * s;
            const int c = slot & 15, r = (slot >> 4) & 15, ch = slot >> 8;
            const float4* p = (const float4*)(in + (size_t)ch * NSTATE + base + r * 128 + c * 8);
            uint4 hi, lo;
            cvt8(p[0], p[1], &hi, &lo);
            char* wp = smem + AL_OFF + (ch * 2) * 4096 + r * 256 + ((c ^ (r & 7)) * 16);
            *(uint4*)wp = hi;
            *(uint4*)(wp + 4096) = lo;
        }
    }
    asm volatile("cp.async.wait_group 0;" ::: "memory");
    __syncthreads();

    if (mma_warp) {
        const int ncol0 = w * 16;
        const int ar = lane & 15, acl = lane >> 4, ar7 = ar & 7;
        const int brow = ncol0 + (lane & 15), bcl = lane >> 4;
        const uint32_t bbase = sb + (uint32_t)brow * 256u;
        const int br7 = brow & 7;
        const int rg = lane >> 2, tg = lane & 3;

        // register-resident U hi mats only (64 regs): [ks][0]=Ur_hi,[ks][1]=Ui_hi
        uint32_t ufh[8][2][4];
        #pragma unroll
        for (int ks = 0; ks < 8; ++ks) {
            const uint32_t ba = bbase + (uint32_t)(((ks * 2 + bcl) ^ br7) << 4);
            LDM4(ufh[ks][0], ba);
            LDM4(ufh[ks][1], ba + 65536);
        }

        uint32_t buf = 0;
        for (; item < 4096; item += 148) {
            float acc0[2][4], acc1[2][4];
            #pragma unroll
            for (int j = 0; j < 2; ++j)
                #pragma unroll
                for (int q = 0; q < 4; ++q) { acc0[j][q] = 0.f; acc1[j][q] = 0.f; }

            const uint32_t abase = sb + AL_OFF + buf * 16384u + (uint32_t)ar * 256u;
            #pragma unroll
            for (int ks = 0; ks < 8; ++ks) {
                uint32_t af[4][4], naf2[4], naf3[4], bl0[4], bl1[4];
                const uint32_t aa = abase + (uint32_t)(((ks * 2 + acl) ^ ar7) << 4);
                LDM4(af[0], aa);              // Sr_hi
                LDM4(af[1], aa + 4096);       // Sr_lo
                LDM4(af[2], aa + 8192);       // Si_hi
                LDM4(af[3], aa + 12288);      // Si_lo
                const uint32_t ba = bbase + (uint32_t)(((ks * 2 + bcl) ^ br7) << 4);
                LDM4(bl0, ba + 32768);        // Ur_lo
                LDM4(bl1, ba + 98304);        // Ui_lo
                #pragma unroll
                for (int q = 0; q < 4; ++q) { naf2[q] = af[2][q] ^ SGN; naf3[q] = af[3][q] ^ SGN; }

                MMA12W(acc0[0], acc1[0], af, naf2, naf3, ufh[ks][0], ufh[ks][1], bl0, bl1, 0)
                MMA12W(acc0[1], acc1[1], af, naf2, naf3, ufh[ks][0], ufh[ks][1], bl0, bl1, 1)
            }

            {
                const size_t row0 = (size_t)item * 16 + rg;
                float* o0 = out;
                float* o1 = out + NSTATE;
                #pragma unroll
                for (int j = 0; j < 2; ++j) {
                    const int n = ncol0 + j * 8 + tg * 2;
                    *(float2*)(o0 + row0 * 128 + n)       = make_float2(acc0[j][0], acc0[j][1]);
                    *(float2*)(o0 + (row0 + 8) * 128 + n) = make_float2(acc0[j][2], acc0[j][3]);
                    *(float2*)(o1 + row0 * 128 + n)       = make_float2(acc1[j][0], acc1[j][1]);
                    *(float2*)(o1 + (row0 + 8) * 128 + n) = make_float2(acc1[j][2], acc1[j][3]);
                }
            }
            __syncthreads();
            buf ^= 1u;
        }
    } else {
        const int pt = t - 256;           // 0..127
        uint32_t buf = 0;
        for (; item < 4096; item += 148) {
            const int next = item + 148;
            if (next < 4096) {
                const size_t base = (size_t)next * 2048;
                #pragma unroll
                for (int s = 0; s < 4; ++s) {
                    const int slot = pt + 128 * s;
                    const int c = slot & 15, r = (slot >> 4) & 15, ch = slot >> 8;
                    const float4* p = (const float4*)(in + (size_t)ch * NSTATE + base + r * 128 + c * 8);
                    uint4 hi, lo;
                    cvt8(p[0], p[1], &hi, &lo);
                    char* wp = smem + AL_OFF + (buf ^ 1u) * 16384u + (ch * 2) * 4096 + r * 256
                             + ((c ^ (r & 7)) * 16);
                    *(uint4*)wp = hi;
                    *(uint4*)(wp + 4096) = lo;
                }
            }
            __syncthreads();
            buf ^= 1u;
        }
    }
}

// ---------------------------------------------------------------------------
// Gate 3 (R12 proven version): persistent 512 threads; A = U k-half in SMEM.
__global__ void __launch_bounds__(512, 1)
gate_highp(const float* __restrict__ in, float* __restrict__ out,
           const __nv_bfloat16* __restrict__ img)
{
    extern __shared__ char smem[];
    const uint32_t sb = smem_u32(smem);
    const int t = threadIdx.x, lane = t & 31, w = t >> 5;
    const int khalf = blockIdx.x & 1;
    const int pairid = blockIdx.x >> 1;   // 0..73

    {
        const uint4* src = (const uint4*)img;
        #pragma unroll
        for (int j = 0; j < 8; ++j) {
            const int idx = t + 512 * j;              // 0..4095
            const int m = idx >> 10, within = idx & 1023;
            CPASYNC16(sb + (uint32_t)idx * 16u, src + m * 2048 + khalf * 1024 + within);
        }
        asm volatile("cp.async.commit_group;" ::: "memory");
    }

    int widx = pairid;                    // 1024 = 512 chunks x 2 l-halves
    {
        const int chunk = widx >> 1, lh = widx & 1;
        const size_t cb = (size_t)chunk * 16384;
        #pragma unroll
        for (int s = 0; s < 4; ++s) {
            const int slot = t + 512 * s;
            const int c = slot & 7, a = (slot >> 3) & 127, ch = slot >> 10;
            const float4* p = (const float4*)(in + (size_t)ch * NSTATE + cb + a * 128 + lh * 64 + c * 8);
            uint4 hi, lo;
            cvt8(p[0], p[1], &hi, &lo);
            char* wp = smem + BH_OFF + (ch * 2) * 16384 + a * 128 + ((c ^ (a & 7)) * 16);
            *(uint4*)wp = hi;
            *(uint4*)(wp + 16384) = lo;
        }
    }
    asm volatile("cp.async.wait_group 0;" ::: "memory");
    __syncthreads();

    const int mrow0 = (w & 3) * 16, ncol0 = (w >> 2) * 16;
    const int ar = mrow0 + (lane & 15), acl = lane >> 4, ar7 = ar & 7;
    const int br_off = (lane & 7) + ((lane & 16) >> 1), bcl = (lane >> 3) & 1;
    const int rg = lane >> 2, tg = lane & 3;
    const uint32_t abase = sb + (uint32_t)ar * 256u;
    const int cidx = (ncol0 >> 3) + bcl;

    uint32_t buf = 0;
    for (; widx < 1024; widx += 74) {
        const int chunk = widx >> 1, lh = widx & 1;
        const size_t cb = (size_t)chunk * 16384;
        const int nwidx = widx + 74;
        const bool hasnext = nwidx < 1024;
        const int nchunk = nwidx >> 1, nlh = nwidx & 1;
        const size_t ncb = (size_t)nchunk * 16384;

        float4 stg[4];
        if (hasnext) {
            #pragma unroll
            for (int s = 0; s < 2; ++s) {
                const int slot = t + 512 * s;
                const int c = slot & 7, a = (slot >> 3) & 127, ch = slot >> 10;
                const float4* p = (const float4*)(in + (size_t)ch * NSTATE + ncb + a * 128 + nlh * 64 + c * 8);
                stg[2 * s] = p[0];
                stg[2 * s + 1] = p[1];
            }
        }

        float acc0[2][4], acc1[2][4];
        #pragma unroll
        for (int j = 0; j < 2; ++j)
            #pragma unroll
            for (int q = 0; q < 4; ++q) { acc0[j][q] = 0.f; acc1[j][q] = 0.f; }

        const uint32_t bbuf = sb + BH_OFF + buf * 65536u;
        #pragma unroll 1
        for (int ks = 0; ks < 8; ++ks) {
            uint32_t af[4][4], naf2[4], naf3[4];
            const uint32_t aa = abase + (uint32_t)(((ks * 2 + acl) ^ ar7) << 4);
            LDM4(af[0], aa);
            LDM4(af[1], aa + 16384);
            LDM4(af[2], aa + 32768);
            LDM4(af[3], aa + 49152);
            #pragma unroll
            for (int q = 0; q < 4; ++q) { naf2[q] = af[2][q] ^ SGN; naf3[q] = af[3][q] ^ SGN; }

            uint32_t bf[4][4];
            const int row = ks * 16 + br_off;
            const uint32_t ba = bbuf + (uint32_t)row * 128u
                              + (uint32_t)((cidx ^ (row & 7)) << 4);
            LDM4T(bf[0], ba);
            LDM4T(bf[1], ba + 16384);
            LDM4T(bf[2], ba + 32768);
            LDM4T(bf[3], ba + 49152);
            MMA12P(acc0[0], acc1[0], af, naf2, naf3, bf, 0)
            MMA12P(acc0[1], acc1[1], af, naf2, naf3, bf, 1)
        }

        if (hasnext) {
            #pragma unroll
            for (int s = 0; s < 2; ++s) {
                const int slot = t + 512 * s;
                const int c = slot & 7, a = (slot >> 3) & 127, ch = slot >> 10;
                uint4 hi, lo;
                cvt8(stg[2 * s], stg[2 * s + 1], &hi, &lo);
                char* wp = smem + BH_OFF + (buf ^ 1u) * 65536u + (ch * 2) * 16384 + a * 128
                         + ((c ^ (a & 7)) * 16);
                *(uint4*)wp = hi;
                *(uint4*)(wp + 16384) = lo;
            }
            #pragma unroll
            for (int s = 2; s < 4; ++s) {
                const int slot = t + 512 * s;
                const int c = slot & 7, a = (slot >> 3) & 127, ch = slot >> 10;
                const float4* p = (const float4*)(in + (size_t)ch * NSTATE + ncb + a * 128 + nlh * 64 + c * 8);
                uint4 hi, lo;
                cvt8(p[0], p[1], &hi, &lo);
                char* wp = smem + BH_OFF + (buf ^ 1u) * 65536u + (ch * 2) * 16384 + a * 128
                         + ((c ^ (a & 7)) * 16);
                *(uint4*)wp = hi;
                *(uint4*)(wp + 16384) = lo;
            }
        }

        {
            const size_t row0 = (size_t)khalf * 64 + mrow0 + rg;
            float* o0 = out + cb;
            float* o1 = out + NSTATE + cb;
            #pragma unroll
            for (int j = 0; j < 2; ++j) {
                const int n = lh * 64 + ncol0 + j * 8 + tg * 2;
                *(float2*)(o0 + row0 * 128 + n)       = make_float2(acc0[j][0], acc0[j][1]);
                *(float2*)(o0 + (row0 + 8) * 128 + n) = make_float2(acc0[j][2], acc0[j][3]);
                *(float2*)(o1 + row0 * 128 + n)       = make_float2(acc1[j][0], acc1[j][1]);
                *(float2*)(o1 + (row0 + 8) * 128 + n) = make_float2(acc1[j][2], acc1[j][3]);
            }
        }
        __syncthreads();
        buf ^= 1u;
    }
}

// ---------------------------------------------------------------------------
extern "C" void kernel_launch(void* const* d_in, const int* in_sizes, int n_in,
                              void* d_out, int out_size)
{
    const float* state = (const float*)d_in[0];
    const float* U     = (const float*)d_in[1];
    if (n_in >= 2 && in_sizes[0] < in_sizes[1]) {
        const float* tmp = state; state = U; U = tmp;
    }
    float* out = (float*)d_out;

    float* scratch = nullptr;
    cudaGetSymbolAddress((void**)&scratch, g_scratch);
    __nv_bfloat16* ubf = nullptr;
    cudaGetSymbolAddress((void**)&ubf, g_ubf);

    cudaFuncSetAttribute(gate_lows,  cudaFuncAttributeMaxDynamicSharedMemorySize, (int)SMEM_BYTES_LO);
    cudaFuncSetAttribute(gate_highp, cudaFuncAttributeMaxDynamicSharedMemorySize, (int)SMEM_BYTES_HI);

    prep_u<<<512, 256>>>(U);
    gate_lows<<<148, 384, SMEM_BYTES_LO>>>(state,   scratch, ubf);            // gate 0
    gate_lows<<<148, 384, SMEM_BYTES_LO>>>(scratch, out,     ubf + 65536);    // gate 1
    gate_lows<<<148, 384, SMEM_BYTES_LO>>>(out,     scratch, ubf + 131072);   // gate 2
    gate_highp<<<148, 512, SMEM_BYTES_HI>>>(scratch, out,    ubf + 196608);   // gate 3
}

// round 16
// speedup vs baseline: 1.1648x; 1.0460x over previous
#include <cuda_runtime.h>
#include <cuda_bf16.h>
#include <cstdint>

#define NSTATE (1u << 23)

__device__ float g_scratch[1u << 24];
__device__ __nv_bfloat16 g_ubf[262144];   // 4 gates x 4 matrices x 16384 bf16

#define SMEM_BYTES_LO 163840u   // U image 128KB + 2 x 16KB state buffers
#define SMEM_BYTES_HI 196608u   // U-half 64KB + 2 x 64KB state buffers
#define SGN 0x80008000u

#define AL_OFF 131072u          // gates 0-2 state buffers
#define BH_OFF 65536u           // gate 3 state buffers

__device__ __forceinline__ uint32_t smem_u32(const void* p) {
    uint32_t a;
    asm("{ .reg .u64 t; cvta.to.shared.u64 t, %1; cvt.u32.u64 %0, t; }" : "=r"(a) : "l"(p));
    return a;
}

#define CPASYNC16(saddr, gptr)                                                  \
    asm volatile("cp.async.cg.shared.global [%0], [%1], 16;"                    \
        :: "r"(saddr), "l"(gptr) : "memory")

#define LDM4(r, addr)                                                           \
    asm volatile("ldmatrix.sync.aligned.m8n8.x4.shared.b16 {%0,%1,%2,%3}, [%4];"\
        : "=r"((r)[0]), "=r"((r)[1]), "=r"((r)[2]), "=r"((r)[3]) : "r"(addr))

#define LDM4T(r, addr)                                                          \
    asm volatile("ldmatrix.sync.aligned.m8n8.x4.trans.shared.b16 {%0,%1,%2,%3}, [%4];"\
        : "=r"((r)[0]), "=r"((r)[1]), "=r"((r)[2]), "=r"((r)[3]) : "r"(addr))

#define MMA(C, A, b0v, b1v)                                                     \
    asm volatile("mma.sync.aligned.m16n8k16.row.col.f32.bf16.bf16.f32 "         \
        "{%0,%1,%2,%3}, {%4,%5,%6,%7}, {%8,%9}, {%0,%1,%2,%3};"                 \
        : "+f"((C)[0]), "+f"((C)[1]), "+f"((C)[2]), "+f"((C)[3])                \
        : "r"((A)[0]), "r"((A)[1]), "r"((A)[2]), "r"((A)[3]), "r"(b0v), "r"(b1v))

// gates 0-2 (A=state, B=U; U-hi reg-resident):
// ch1 = Sr*Ur - Si*Ui ; ch0 = Si*Ur + Sr*Ui
#define MMA12W(ACC0, ACC1, AF, N2, N3, UH0, UH1, BL0, BL1, J2)                  \
    MMA(ACC1, AF[0], UH0[J2], UH0[(J2) + 2]);                                   \
    MMA(ACC1, AF[0], BL0[J2], BL0[(J2) + 2]);                                   \
    MMA(ACC1, AF[1], UH0[J2], UH0[(J2) + 2]);                                   \
    MMA(ACC1, N2,    UH1[J2], UH1[(J2) + 2]);                                   \
    MMA(ACC1, N2,    BL1[J2], BL1[(J2) + 2]);                                   \
    MMA(ACC1, N3,    UH1[J2], UH1[(J2) + 2]);                                   \
    MMA(ACC0, AF[2], UH0[J2], UH0[(J2) + 2]);                                   \
    MMA(ACC0, AF[2], BL0[J2], BL0[(J2) + 2]);                                   \
    MMA(ACC0, AF[3], UH0[J2], UH0[(J2) + 2]);                                   \
    MMA(ACC0, AF[0], UH1[J2], UH1[(J2) + 2]);                                   \
    MMA(ACC0, AF[0], BL1[J2], BL1[(J2) + 2]);                                   \
    MMA(ACC0, AF[1], UH1[J2], UH1[(J2) + 2]);

// gate 3 (A=U with hi reg-resident, B=state; signs on B side):
// ch1 = Ur*Sr - Ui*Si ; ch0 = Ur*Si + Ui*Sr
#define MMA12H(ACC0, ACC1, UH0, UH1, AL0, AL1, BF, NB2, NB3, J2)                \
    MMA(ACC1, UH0, BF[0][J2], BF[0][(J2) + 2]);                                 \
    MMA(ACC1, UH0, BF[1][J2], BF[1][(J2) + 2]);                                 \
    MMA(ACC1, AL0, BF[0][J2], BF[0][(J2) + 2]);                                 \
    MMA(ACC1, UH1, NB2[J2],   NB2[(J2) + 2]);                                   \
    MMA(ACC1, UH1, NB3[J2],   NB3[(J2) + 2]);                                   \
    MMA(ACC1, AL1, NB2[J2],   NB2[(J2) + 2]);                                   \
    MMA(ACC0, UH0, BF[2][J2], BF[2][(J2) + 2]);                                 \
    MMA(ACC0, UH0, BF[3][J2], BF[3][(J2) + 2]);                                 \
    MMA(ACC0, AL0, BF[2][J2], BF[2][(J2) + 2]);                                 \
    MMA(ACC0, UH1, BF[0][J2], BF[0][(J2) + 2]);                                 \
    MMA(ACC0, UH1, BF[1][J2], BF[1][(J2) + 2]);                                 \
    MMA(ACC0, AL1, BF[0][J2], BF[0][(J2) + 2]);

// fp32 x8 -> bf16 hi (16B) + bf16 lo (16B)
__device__ __forceinline__ void cvt8(float4 x, float4 y, uint4* hi, uint4* lo) {
    float f[8] = {x.x, x.y, x.z, x.w, y.x, y.y, y.z, y.w};
    uint32_t h[8], l[8];
    #pragma unroll
    for (int i = 0; i < 8; ++i) {
        __nv_bfloat16 hb = __float2bfloat16(f[i]);
        h[i] = (uint32_t)__bfloat16_as_ushort(hb);
        l[i] = (uint32_t)__bfloat16_as_ushort(__float2bfloat16(f[i] - __bfloat162float(hb)));
    }
    *hi = make_uint4(h[0] | (h[1] << 16), h[2] | (h[3] << 16),
                     h[4] | (h[5] << 16), h[6] | (h[7] << 16));
    *lo = make_uint4(l[0] | (l[1] << 16), l[2] | (l[3] << 16),
                     l[4] | (l[5] << 16), l[6] | (l[7] << 16));
}

// ---------------------------------------------------------------------------
__global__ void prep_u(const float* __restrict__ U)
{
    const int i = blockIdx.x * 256 + threadIdx.x;   // 131072
    const int a = i & 127, k = (i >> 7) & 127, c = (i >> 14) & 1, g = i >> 15;
    const float x = U[i];
    const __nv_bfloat16 hi = __float2bfloat16(x);
    const __nv_bfloat16 lo = __float2bfloat16(x - __bfloat162float(hi));
    const int h = k * 128 + (((a >> 3) ^ (k & 7)) << 3) + (a & 7);
    g_ubf[g * 65536 + (c * 2 + 0) * 16384 + h] = hi;
    g_ubf[g * 65536 + (c * 2 + 1) * 16384 + h] = lo;
}

// ---------------------------------------------------------------------------
// Gates 0-2, WARP-SPECIALIZED (R15, unchanged): 384 threads.
__global__ void __launch_bounds__(384, 1)
gate_lows(const float* __restrict__ in, float* __restrict__ out,
          const __nv_bfloat16* __restrict__ img)
{
    extern __shared__ char smem[];
    const uint32_t sb = smem_u32(smem);
    const int t = threadIdx.x, lane = t & 31, w = t >> 5;
    const bool mma_warp = (w < 8);

    for (int idx = t; idx < 8192; idx += 384)
        CPASYNC16(sb + (uint32_t)idx * 16u, ((const uint4*)img) + idx);
    asm volatile("cp.async.commit_group;" ::: "memory");

    int item = blockIdx.x;
    if (!mma_warp) {
        const int pt = t - 256;
        const size_t base = (size_t)item * 2048;
        #pragma unroll
        for (int s = 0; s < 4; ++s) {
            const int slot = pt + 128 * s;
            const int c = slot & 15, r = (slot >> 4) & 15, ch = slot >> 8;
            const float4* p = (const float4*)(in + (size_t)ch * NSTATE + base + r * 128 + c * 8);
            uint4 hi, lo;
            cvt8(p[0], p[1], &hi, &lo);
            char* wp = smem + AL_OFF + (ch * 2) * 4096 + r * 256 + ((c ^ (r & 7)) * 16);
            *(uint4*)wp = hi;
            *(uint4*)(wp + 4096) = lo;
        }
    }
    asm volatile("cp.async.wait_group 0;" ::: "memory");
    __syncthreads();

    if (mma_warp) {
        const int ncol0 = w * 16;
        const int ar = lane & 15, acl = lane >> 4, ar7 = ar & 7;
        const int brow = ncol0 + (lane & 15), bcl = lane >> 4;
        const uint32_t bbase = sb + (uint32_t)brow * 256u;
        const int br7 = brow & 7;
        const int rg = lane >> 2, tg = lane & 3;

        uint32_t ufh[8][2][4];
        #pragma unroll
        for (int ks = 0; ks < 8; ++ks) {
            const uint32_t ba = bbase + (uint32_t)(((ks * 2 + bcl) ^ br7) << 4);
            LDM4(ufh[ks][0], ba);
            LDM4(ufh[ks][1], ba + 65536);
        }

        uint32_t buf = 0;
        for (; item < 4096; item += 148) {
            float acc0[2][4], acc1[2][4];
            #pragma unroll
            for (int j = 0; j < 2; ++j)
                #pragma unroll
                for (int q = 0; q < 4; ++q) { acc0[j][q] = 0.f; acc1[j][q] = 0.f; }

            const uint32_t abase = sb + AL_OFF + buf * 16384u + (uint32_t)ar * 256u;
            #pragma unroll
            for (int ks = 0; ks < 8; ++ks) {
                uint32_t af[4][4], naf2[4], naf3[4], bl0[4], bl1[4];
                const uint32_t aa = abase + (uint32_t)(((ks * 2 + acl) ^ ar7) << 4);
                LDM4(af[0], aa);
                LDM4(af[1], aa + 4096);
                LDM4(af[2], aa + 8192);
                LDM4(af[3], aa + 12288);
                const uint32_t ba = bbase + (uint32_t)(((ks * 2 + bcl) ^ br7) << 4);
                LDM4(bl0, ba + 32768);
                LDM4(bl1, ba + 98304);
                #pragma unroll
                for (int q = 0; q < 4; ++q) { naf2[q] = af[2][q] ^ SGN; naf3[q] = af[3][q] ^ SGN; }

                MMA12W(acc0[0], acc1[0], af, naf2, naf3, ufh[ks][0], ufh[ks][1], bl0, bl1, 0)
                MMA12W(acc0[1], acc1[1], af, naf2, naf3, ufh[ks][0], ufh[ks][1], bl0, bl1, 1)
            }

            {
                const size_t row0 = (size_t)item * 16 + rg;
                float* o0 = out;
                float* o1 = out + NSTATE;
                #pragma unroll
                for (int j = 0; j < 2; ++j) {
                    const int n = ncol0 + j * 8 + tg * 2;
                    *(float2*)(o0 + row0 * 128 + n)       = make_float2(acc0[j][0], acc0[j][1]);
                    *(float2*)(o0 + (row0 + 8) * 128 + n) = make_float2(acc0[j][2], acc0[j][3]);
                    *(float2*)(o1 + row0 * 128 + n)       = make_float2(acc1[j][0], acc1[j][1]);
                    *(float2*)(o1 + (row0 + 8) * 128 + n) = make_float2(acc1[j][2], acc1[j][3]);
                }
            }
            __syncthreads();
            buf ^= 1u;
        }
    } else {
        const int pt = t - 256;
        uint32_t buf = 0;
        for (; item < 4096; item += 148) {
            const int next = item + 148;
            if (next < 4096) {
                const size_t base = (size_t)next * 2048;
                #pragma unroll
                for (int s = 0; s < 4; ++s) {
                    const int slot = pt + 128 * s;
                    const int c = slot & 15, r = (slot >> 4) & 15, ch = slot >> 8;
                    const float4* p = (const float4*)(in + (size_t)ch * NSTATE + base + r * 128 + c * 8);
                    uint4 hi, lo;
                    cvt8(p[0], p[1], &hi, &lo);
                    char* wp = smem + AL_OFF + (buf ^ 1u) * 16384u + (ch * 2) * 4096 + r * 256
                             + ((c ^ (r & 7)) * 16);
                    *(uint4*)wp = hi;
                    *(uint4*)(wp + 4096) = lo;
                }
            }
            __syncthreads();
            buf ^= 1u;
        }
    }
}

// ---------------------------------------------------------------------------
// Gate 3, WARP-SPECIALIZED: 384 threads.
// Warps 0-7: MMA consumers, 16 k-rows x 32 l-cols each; U-hi mats in registers.
// Warps 8-11: producers converting the next item (2048 slots, 16/thread).
__global__ void __launch_bounds__(384, 1)
gate_highs(const float* __restrict__ in, float* __restrict__ out,
           const __nv_bfloat16* __restrict__ img)
{
    extern __shared__ char smem[];
    const uint32_t sb = smem_u32(smem);
    const int t = threadIdx.x, lane = t & 31, w = t >> 5;
    const bool mma_warp = (w < 8);
    const int khalf = blockIdx.x & 1;
    const int pairid = blockIdx.x >> 1;   // 0..73

    // stage U k-half once (64KB, pre-swizzled; 64 rows per matrix)
    {
        const uint4* src = (const uint4*)img;
        for (int idx = t; idx < 4096; idx += 384) {
            const int m = idx >> 10, within = idx & 1023;
            CPASYNC16(sb + (uint32_t)idx * 16u, src + m * 2048 + khalf * 1024 + within);
        }
        asm volatile("cp.async.commit_group;" ::: "memory");
    }

    int widx = pairid;                    // 1024 = 512 chunks x 2 l-halves
    if (!mma_warp) {
        const int pt = t - 256;           // 0..127
        const int chunk = widx >> 1, lh = widx & 1;
        const size_t cb = (size_t)chunk * 16384;
        #pragma unroll
        for (int s = 0; s < 16; ++s) {
            const int slot = pt + 128 * s;
            const int c = slot & 7, a = (slot >> 3) & 127, ch = slot >> 10;
            const float4* p = (const float4*)(in + (size_t)ch * NSTATE + cb + a * 128 + lh * 64 + c * 8);
            uint4 hi, lo;
            cvt8(p[0], p[1], &hi, &lo);
            char* wp = smem + BH_OFF + (ch * 2) * 16384 + a * 128 + ((c ^ (a & 7)) * 16);
            *(uint4*)wp = hi;
            *(uint4*)(wp + 16384) = lo;
        }
    }
    asm volatile("cp.async.wait_group 0;" ::: "memory");
    __syncthreads();

    if (mma_warp) {
        const int mrow0 = (w & 3) * 16, ncol0 = (w >> 2) * 32;
        const int ar = mrow0 + (lane & 15), acl = lane >> 4, ar7 = ar & 7;
        const int br_off = (lane & 7) + ((lane & 16) >> 1), bcl = (lane >> 3) & 1;
        const int rg = lane >> 2, tg = lane & 3;
        const uint32_t abase = sb + (uint32_t)ar * 256u;
        const int cidx0 = (ncol0 >> 3) + bcl;
        const int cidx1 = cidx0 + 2;

        // register-resident U hi mats (64 regs): [ks][0]=Ur_hi, [ks][1]=Ui_hi
        uint32_t auh[8][2][4];
        #pragma unroll
        for (int ks = 0; ks < 8; ++ks) {
            const uint32_t aa = abase + (uint32_t)(((ks * 2 + acl) ^ ar7) << 4);
            LDM4(auh[ks][0], aa);
            LDM4(auh[ks][1], aa + 32768);
        }

        uint32_t buf = 0;
        for (; widx < 1024; widx += 74) {
            const int chunk = widx >> 1, lh = widx & 1;
            const size_t cb = (size_t)chunk * 16384;

            float acc0[4][4], acc1[4][4];
            #pragma unroll
            for (int j = 0; j < 4; ++j)
                #pragma unroll
                for (int q = 0; q < 4; ++q) { acc0[j][q] = 0.f; acc1[j][q] = 0.f; }

            const uint32_t bbuf = sb + BH_OFF + buf * 65536u;
            #pragma unroll
            for (int ks = 0; ks < 8; ++ks) {
                uint32_t al0[4], al1[4];
                const uint32_t aa = abase + (uint32_t)(((ks * 2 + acl) ^ ar7) << 4);
                LDM4(al0, aa + 16384);        // Ur_lo
                LDM4(al1, aa + 49152);        // Ui_lo

                const int row = ks * 16 + br_off;
                const uint32_t rb = bbuf + (uint32_t)row * 128u;
                const int r7 = row & 7;
                // group 0
                {
                    uint32_t bf[4][4], nb2[4], nb3[4];
                    const uint32_t ba = rb + (uint32_t)((cidx0 ^ r7) << 4);
                    LDM4T(bf[0], ba);             // Sr_hi
                    LDM4T(bf[1], ba + 16384);     // Sr_lo
                    LDM4T(bf[2], ba + 32768);     // Si_hi
                    LDM4T(bf[3], ba + 49152);     // Si_lo
                    #pragma unroll
                    for (int q = 0; q < 4; ++q) { nb2[q] = bf[2][q] ^ SGN; nb3[q] = bf[3][q] ^ SGN; }
                    MMA12H(acc0[0], acc1[0], auh[ks][0], auh[ks][1], al0, al1, bf, nb2, nb3, 0)
                    MMA12H(acc0[1], acc1[1], auh[ks][0], auh[ks][1], al0, al1, bf, nb2, nb3, 1)
                }
                // group 1
                {
                    uint32_t bf[4][4], nb2[4], nb3[4];
                    const uint32_t ba = rb + (uint32_t)((cidx1 ^ r7) << 4);
                    LDM4T(bf[0], ba);
                    LDM4T(bf[1], ba + 16384);
                    LDM4T(bf[2], ba + 32768);
                    LDM4T(bf[3], ba + 49152);
                    #pragma unroll
                    for (int q = 0; q < 4; ++q) { nb2[q] = bf[2][q] ^ SGN; nb3[q] = bf[3][q] ^ SGN; }
                    MMA12H(acc0[2], acc1[2], auh[ks][0], auh[ks][1], al0, al1, bf, nb2, nb3, 0)
                    MMA12H(acc0[3], acc1[3], auh[ks][0], auh[ks][1], al0, al1, bf, nb2, nb3, 1)
                }
            }

            {
                const size_t row0 = (size_t)khalf * 64 + mrow0 + rg;
                float* o0 = out + cb;
                float* o1 = out + NSTATE + cb;
                #pragma unroll
                for (int g = 0; g < 2; ++g)
                    #pragma unroll
                    for (int j2 = 0; j2 < 2; ++j2) {
                        const int j = g * 2 + j2;
                        const int n = lh * 64 + ncol0 + g * 16 + j2 * 8 + tg * 2;
                        *(float2*)(o0 + row0 * 128 + n)       = make_float2(acc0[j][0], acc0[j][1]);
                        *(float2*)(o0 + (row0 + 8) * 128 + n) = make_float2(acc0[j][2], acc0[j][3]);
                        *(float2*)(o1 + row0 * 128 + n)       = make_float2(acc1[j][0], acc1[j][1]);
                        *(float2*)(o1 + (row0 + 8) * 128 + n) = make_float2(acc1[j][2], acc1[j][3]);
                    }
            }
            __syncthreads();
            buf ^= 1u;
        }
    } else {
        const int pt = t - 256;           // 0..127
        uint32_t buf = 0;
        for (; widx < 1024; widx += 74) {
            const int nwidx = widx + 74;
            if (nwidx < 1024) {
                const int nchunk = nwidx >> 1, nlh = nwidx & 1;
                const size_t ncb = (size_t)nchunk * 16384;
                #pragma unroll
                for (int s = 0; s < 16; ++s) {
                    const int slot = pt + 128 * s;
                    const int c = slot & 7, a = (slot >> 3) & 127, ch = slot >> 10;
                    const float4* p = (const float4*)(in + (size_t)ch * NSTATE + ncb + a * 128 + nlh * 64 + c * 8);
                    uint4 hi, lo;
                    cvt8(p[0], p[1], &hi, &lo);
                    char* wp = smem + BH_OFF + (buf ^ 1u) * 65536u + (ch * 2) * 16384 + a * 128
                             + ((c ^ (a & 7)) * 16);
                    *(uint4*)wp = hi;
                    *(uint4*)(wp + 16384) = lo;
                }
            }
            __syncthreads();
            buf ^= 1u;
        }
    }
}

// ---------------------------------------------------------------------------
extern "C" void kernel_launch(void* const* d_in, const int* in_sizes, int n_in,
                              void* d_out, int out_size)
{
    const float* state = (const float*)d_in[0];
    const float* U     = (const float*)d_in[1];
    if (n_in >= 2 && in_sizes[0] < in_sizes[1]) {
        const float* tmp = state; state = U; U = tmp;
    }
    float* out = (float*)d_out;

    float* scratch = nullptr;
    cudaGetSymbolAddress((void**)&scratch, g_scratch);
    __nv_bfloat16* ubf = nullptr;
    cudaGetSymbolAddress((void**)&ubf, g_ubf);

    cudaFuncSetAttribute(gate_lows,  cudaFuncAttributeMaxDynamicSharedMemorySize, (int)SMEM_BYTES_LO);
    cudaFuncSetAttribute(gate_highs, cudaFuncAttributeMaxDynamicSharedMemorySize, (int)SMEM_BYTES_HI);

    prep_u<<<512, 256>>>(U);
    gate_lows<<<148, 384, SMEM_BYTES_LO>>>(state,   scratch, ubf);            // gate 0
    gate_lows<<<148, 384, SMEM_BYTES_LO>>>(scratch, out,     ubf + 65536);    // gate 1
    gate_lows<<<148, 384, SMEM_BYTES_LO>>>(out,     scratch, ubf + 131072);   // gate 2
    gate_highs<<<148, 384, SMEM_BYTES_HI>>>(scratch, out,    ubf + 196608);   // gate 3
}

// round 17
// speedup vs baseline: 1.2424x; 1.0666x over previous
#include <cuda_runtime.h>
#include <cuda_bf16.h>
#include <cstdint>

#define NSTATE (1u << 23)

__device__ float g_scratch[1u << 24];
__device__ __nv_bfloat16 g_ubf[393216];  // 4 gates x 6 mats x 16384 bf16

// gates 0-2 (Gauss): lo mats resident [0,98304) (Ur_lo,Ui_lo,Up_lo @ 32KB each),
// state buffers at 98304 + buf*24576 (6 planes x 4KB). Hi mats staged via state area.
#define ST_OFF 98304u
#define SMEM_BYTES_LOG 147456u
// gate 3 (R16): U-half 64KB + 2 x 64KB state buffers
#define BH_OFF 65536u
#define SMEM_BYTES_HI 196608u
#define SGN 0x80008000u

__device__ __forceinline__ uint32_t smem_u32(const void* p) {
    uint32_t a;
    asm("{ .reg .u64 t; cvta.to.shared.u64 t, %1; cvt.u32.u64 %0, t; }" : "=r"(a) : "l"(p));
    return a;
}

#define CPASYNC16(saddr, gptr)                                                  \
    asm volatile("cp.async.cg.shared.global [%0], [%1], 16;"                    \
        :: "r"(saddr), "l"(gptr) : "memory")

#define LDM4(r, addr)                                                           \
    asm volatile("ldmatrix.sync.aligned.m8n8.x4.shared.b16 {%0,%1,%2,%3}, [%4];"\
        : "=r"((r)[0]), "=r"((r)[1]), "=r"((r)[2]), "=r"((r)[3]) : "r"(addr))

#define LDM4T(r, addr)                                                          \
    asm volatile("ldmatrix.sync.aligned.m8n8.x4.trans.shared.b16 {%0,%1,%2,%3}, [%4];"\
        : "=r"((r)[0]), "=r"((r)[1]), "=r"((r)[2]), "=r"((r)[3]) : "r"(addr))

#define MMA(C, A, b0v, b1v)                                                     \
    asm volatile("mma.sync.aligned.m16n8k16.row.col.f32.bf16.bf16.f32 "         \
        "{%0,%1,%2,%3}, {%4,%5,%6,%7}, {%8,%9}, {%0,%1,%2,%3};"                 \
        : "+f"((C)[0]), "+f"((C)[1]), "+f"((C)[2]), "+f"((C)[3])                \
        : "r"((A)[0]), "r"((A)[1]), "r"((A)[2]), "r"((A)[3]), "r"(b0v), "r"(b1v))

// gate 3 (unchanged R16): A=U hi reg-resident, B=state; signs on B side.
#define MMA12H(ACC0, ACC1, UH0, UH1, AL0, AL1, BF, NB2, NB3, J2)                \
    MMA(ACC1, UH0, BF[0][J2], BF[0][(J2) + 2]);                                 \
    MMA(ACC1, UH0, BF[1][J2], BF[1][(J2) + 2]);                                 \
    MMA(ACC1, AL0, BF[0][J2], BF[0][(J2) + 2]);                                 \
    MMA(ACC1, UH1, NB2[J2],   NB2[(J2) + 2]);                                   \
    MMA(ACC1, UH1, NB3[J2],   NB3[(J2) + 2]);                                   \
    MMA(ACC1, AL1, NB2[J2],   NB2[(J2) + 2]);                                   \
    MMA(ACC0, UH0, BF[2][J2], BF[2][(J2) + 2]);                                 \
    MMA(ACC0, UH0, BF[3][J2], BF[3][(J2) + 2]);                                 \
    MMA(ACC0, AL0, BF[2][J2], BF[2][(J2) + 2]);                                 \
    MMA(ACC0, UH1, BF[0][J2], BF[0][(J2) + 2]);                                 \
    MMA(ACC0, UH1, BF[1][J2], BF[1][(J2) + 2]);                                 \
    MMA(ACC0, AL1, BF[0][J2], BF[0][(J2) + 2]);

__device__ __forceinline__ void cvt8(float4 x, float4 y, uint4* hi, uint4* lo) {
    float f[8] = {x.x, x.y, x.z, x.w, y.x, y.y, y.z, y.w};
    uint32_t h[8], l[8];
    #pragma unroll
    for (int i = 0; i < 8; ++i) {
        __nv_bfloat16 hb = __float2bfloat16(f[i]);
        h[i] = (uint32_t)__bfloat16_as_ushort(hb);
        l[i] = (uint32_t)__bfloat16_as_ushort(__float2bfloat16(f[i] - __bfloat162float(hb)));
    }
    *hi = make_uint4(h[0] | (h[1] << 16), h[2] | (h[3] << 16),
                     h[4] | (h[5] << 16), h[6] | (h[7] << 16));
    *lo = make_uint4(l[0] | (l[1] << 16), l[2] | (l[3] << 16),
                     l[4] | (l[5] << 16), l[6] | (l[7] << 16));
}

// ---------------------------------------------------------------------------
// Per gate: mats 0..5 = Ur_hi, Ur_lo, Ui_hi, Ui_lo, Up_hi, Up_lo (Up = Ur+Ui)
__global__ void prep_u(const float* __restrict__ U)
{
    const int i = blockIdx.x * 256 + threadIdx.x;   // 65536 = 4 gates x 16384
    const int e = i & 16383, g = i >> 14;
    const int a = e & 127, k = e >> 7;
    const float ur = U[g * 32768 + e];
    const float ui = U[g * 32768 + 16384 + e];
    const float up = ur + ui;
    const int h = k * 128 + (((a >> 3) ^ (k & 7)) << 3) + (a & 7);
    __nv_bfloat16* dst = g_ubf + g * 98304;
    __nv_bfloat16 hr = __float2bfloat16(ur);
    dst[h]             = hr;
    dst[16384 + h]     = __float2bfloat16(ur - __bfloat162float(hr));
    __nv_bfloat16 hb = __float2bfloat16(ui);
    dst[32768 + h]     = hb;
    dst[49152 + h]     = __float2bfloat16(ui - __bfloat162float(hb));
    __nv_bfloat16 hp = __float2bfloat16(up);
    dst[65536 + h]     = hp;
    dst[81920 + h]     = __float2bfloat16(up - __bfloat162float(hp));
}

// ---------------------------------------------------------------------------
// Gates 0-2, GAUSS 3-product, warp-specialized: 384 threads.
// Warps 0-7: MMA consumers (16 cols each; Ur_hi/Ui_hi/Up_hi register-resident).
// Warps 8-11: producers (LDG + Sp=Sr+Si + bf16 split for next item, 6 planes).
__global__ void __launch_bounds__(384, 1)
gate_lowg(const float* __restrict__ in, float* __restrict__ out,
          const __nv_bfloat16* __restrict__ img)
{
    extern __shared__ char smem[];
    const uint32_t sb = smem_u32(smem);
    const int t = threadIdx.x, lane = t & 31, w = t >> 5;
    const bool mma_warp = (w < 8);
    const uint4* usrc = (const uint4*)img;   // 6 mats x 2048 uint4

    // consumer addressing (computed by all threads; cheap)
    const int ncol0 = w * 16;
    const int ar = lane & 15, acl = lane >> 4, ar7 = ar & 7;
    const int brow = (ncol0 & 127) + (lane & 15), bcl = lane >> 4;
    const int br7 = brow & 7;
    const int rg = lane >> 2, tg = lane & 3;

    // resident lo mats: Ur_lo -> 0, Ui_lo -> 32768, Up_lo -> 65536
    #pragma unroll
    for (int m = 0; m < 3; ++m)
        for (int idx = t; idx < 2048; idx += 384)
            CPASYNC16(sb + (uint32_t)m * 32768u + (uint32_t)idx * 16u,
                      usrc + (2 * m + 1) * 2048 + idx);
    asm volatile("cp.async.commit_group;" ::: "memory");

    // stage hi mats through state area, load fragments to registers
    uint32_t urh[8][4], uih[8][4], uph[8][4];
#define STAGE_HI(MAT, DEST)                                                     \
    for (int idx = t; idx < 2048; idx += 384)                                   \
        CPASYNC16(sb + ST_OFF + (uint32_t)idx * 16u, usrc + (MAT) * 2048 + idx);\
    asm volatile("cp.async.commit_group;" ::: "memory");                        \
    asm volatile("cp.async.wait_group 0;" ::: "memory");                        \
    __syncthreads();                                                            \
    if (mma_warp) {                                                             \
        _Pragma("unroll")                                                       \
        for (int ks = 0; ks < 8; ++ks) {                                        \
            const uint32_t ba = sb + ST_OFF + (uint32_t)brow * 256u             \
                              + (uint32_t)(((ks * 2 + bcl) ^ br7) << 4);        \
            LDM4(DEST[ks], ba);                                                 \
        }                                                                       \
    }                                                                           \
    __syncthreads();

    STAGE_HI(0, urh)
    STAGE_HI(2, uih)
    STAGE_HI(4, uph)
#undef STAGE_HI

    int item = blockIdx.x;
    // producers convert first item into buf 0 (256 slots, 2/thread)
    if (!mma_warp) {
        const int pt = t - 256;
        const size_t base = (size_t)item * 2048;
        #pragma unroll
        for (int s = 0; s < 2; ++s) {
            const int slot = pt + 128 * s;
            const int c = slot & 15, r = slot >> 4;
            const float4* p0 = (const float4*)(in + base + r * 128 + c * 8);
            const float4* p1 = (const float4*)(in + NSTATE + base + r * 128 + c * 8);
            float4 x0 = p0[0], x1 = p0[1], y0 = p1[0], y1 = p1[1];
            float4 s0 = make_float4(x0.x + y0.x, x0.y + y0.y, x0.z + y0.z, x0.w + y0.w);
            float4 s1 = make_float4(x1.x + y1.x, x1.y + y1.y, x1.z + y1.z, x1.w + y1.w);
            uint4 hr, lr, hh, ll, hp, lp;
            cvt8(x0, x1, &hr, &lr);
            cvt8(y0, y1, &hh, &ll);
            cvt8(s0, s1, &hp, &lp);
            char* wp = smem + ST_OFF + r * 256 + ((c ^ (r & 7)) * 16);
            *(uint4*)(wp)         = hr;
            *(uint4*)(wp + 4096)  = lr;
            *(uint4*)(wp + 8192)  = hh;
            *(uint4*)(wp + 12288) = ll;
            *(uint4*)(wp + 16384) = hp;
            *(uint4*)(wp + 20480) = lp;
        }
    }
    __syncthreads();

    if (mma_warp) {
        uint32_t buf = 0;
        for (; item < 4096; item += 148) {
            float aWr[2][4], aWi[2][4], aP[2][4];
            #pragma unroll
            for (int j = 0; j < 2; ++j)
                #pragma unroll
                for (int q = 0; q < 4; ++q) { aWr[j][q] = 0.f; aWi[j][q] = 0.f; aP[j][q] = 0.f; }

            const uint32_t abase = sb + ST_OFF + buf * 24576u + (uint32_t)ar * 256u;
            const uint32_t bb = sb + (uint32_t)brow * 256u;
            #pragma unroll
            for (int ks = 0; ks < 8; ++ks) {
                const uint32_t aa = abase + (uint32_t)(((ks * 2 + acl) ^ ar7) << 4);
                const uint32_t bo = bb + (uint32_t)(((ks * 2 + bcl) ^ br7) << 4);
                uint32_t srh[4], srl[4], url[4];
                LDM4(srh, aa);
                LDM4(srl, aa + 4096);
                LDM4(url, bo);
                #pragma unroll
                for (int j = 0; j < 2; ++j) {
                    MMA(aWr[j], srh, urh[ks][j], urh[ks][j + 2]);
                    MMA(aWr[j], srh, url[j],     url[j + 2]);
                    MMA(aWr[j], srl, urh[ks][j], urh[ks][j + 2]);
                }
                uint32_t sih[4], sil[4], uil[4];
                LDM4(sih, aa + 8192);
                LDM4(sil, aa + 12288);
                LDM4(uil, bo + 32768);
                #pragma unroll
                for (int j = 0; j < 2; ++j) {
                    MMA(aWi[j], sih, uih[ks][j], uih[ks][j + 2]);
                    MMA(aWi[j], sih, uil[j],     uil[j + 2]);
                    MMA(aWi[j], sil, uih[ks][j], uih[ks][j + 2]);
                }
                uint32_t sph[4], spl[4], upl[4];
                LDM4(sph, aa + 16384);
                LDM4(spl, aa + 20480);
                LDM4(upl, bo + 65536);
                #pragma unroll
                for (int j = 0; j < 2; ++j) {
                    MMA(aP[j], sph, uph[ks][j], uph[ks][j + 2]);
                    MMA(aP[j], sph, upl[j],     upl[j + 2]);
                    MMA(aP[j], spl, uph[ks][j], uph[ks][j + 2]);
                }
            }

            // epilogue: ch1 = Wr - Wi ; ch0 = P - Wr - Wi
            {
                const size_t row0 = (size_t)item * 16 + rg;
                float* o0 = out;
                float* o1 = out + NSTATE;
                #pragma unroll
                for (int j = 0; j < 2; ++j) {
                    const int n = ncol0 + j * 8 + tg * 2;
                    float c1[4], c0[4];
                    #pragma unroll
                    for (int q = 0; q < 4; ++q) {
                        c1[q] = aWr[j][q] - aWi[j][q];
                        c0[q] = aP[j][q] - aWr[j][q] - aWi[j][q];
                    }
                    *(float2*)(o0 + row0 * 128 + n)       = make_float2(c0[0], c0[1]);
                    *(float2*)(o0 + (row0 + 8) * 128 + n) = make_float2(c0[2], c0[3]);
                    *(float2*)(o1 + row0 * 128 + n)       = make_float2(c1[0], c1[1]);
                    *(float2*)(o1 + (row0 + 8) * 128 + n) = make_float2(c1[2], c1[3]);
                }
            }
            __syncthreads();
            buf ^= 1u;
        }
    } else {
        const int pt = t - 256;
        uint32_t buf = 0;
        for (; item < 4096; item += 148) {
            const int next = item + 148;
            if (next < 4096) {
                const size_t base = (size_t)next * 2048;
                #pragma unroll
                for (int s = 0; s < 2; ++s) {
                    const int slot = pt + 128 * s;
                    const int c = slot & 15, r = slot >> 4;
                    const float4* p0 = (const float4*)(in + base + r * 128 + c * 8);
                    const float4* p1 = (const float4*)(in + NSTATE + base + r * 128 + c * 8);
                    float4 x0 = p0[0], x1 = p0[1], y0 = p1[0], y1 = p1[1];
                    float4 s0 = make_float4(x0.x + y0.x, x0.y + y0.y, x0.z + y0.z, x0.w + y0.w);
                    float4 s1 = make_float4(x1.x + y1.x, x1.y + y1.y, x1.z + y1.z, x1.w + y1.w);
                    uint4 hr, lr, hh, ll, hp, lp;
                    cvt8(x0, x1, &hr, &lr);
                    cvt8(y0, y1, &hh, &ll);
                    cvt8(s0, s1, &hp, &lp);
                    char* wp = smem + ST_OFF + (buf ^ 1u) * 24576u + r * 256 + ((c ^ (r & 7)) * 16);
                    *(uint4*)(wp)         = hr;
                    *(uint4*)(wp + 4096)  = lr;
                    *(uint4*)(wp + 8192)  = hh;
                    *(uint4*)(wp + 12288) = ll;
                    *(uint4*)(wp + 16384) = hp;
                    *(uint4*)(wp + 20480) = lp;
                }
            }
            __syncthreads();
            buf ^= 1u;
        }
    }
}

// ---------------------------------------------------------------------------
// Gate 3 (R16 proven, unchanged): warp-specialized, 384 threads.
__global__ void __launch_bounds__(384, 1)
gate_highs(const float* __restrict__ in, float* __restrict__ out,
           const __nv_bfloat16* __restrict__ img)
{
    extern __shared__ char smem[];
    const uint32_t sb = smem_u32(smem);
    const int t = threadIdx.x, lane = t & 31, w = t >> 5;
    const bool mma_warp = (w < 8);
    const int khalf = blockIdx.x & 1;
    const int pairid = blockIdx.x >> 1;

    {
        const uint4* src = (const uint4*)img;
        for (int idx = t; idx < 4096; idx += 384) {
            const int m = idx >> 10, within = idx & 1023;
            CPASYNC16(sb + (uint32_t)idx * 16u, src + m * 2048 + khalf * 1024 + within);
        }
        asm volatile("cp.async.commit_group;" ::: "memory");
    }

    int widx = pairid;
    if (!mma_warp) {
        const int pt = t - 256;
        const int chunk = widx >> 1, lh = widx & 1;
        const size_t cb = (size_t)chunk * 16384;
        #pragma unroll
        for (int s = 0; s < 16; ++s) {
            const int slot = pt + 128 * s;
            const int c = slot & 7, a = (slot >> 3) & 127, ch = slot >> 10;
            const float4* p = (const float4*)(in + (size_t)ch * NSTATE + cb + a * 128 + lh * 64 + c * 8);
            uint4 hi, lo;
            cvt8(p[0], p[1], &hi, &lo);
            char* wp = smem + BH_OFF + (ch * 2) * 16384 + a * 128 + ((c ^ (a & 7)) * 16);
            *(uint4*)wp = hi;
            *(uint4*)(wp + 16384) = lo;
        }
    }
    asm volatile("cp.async.wait_group 0;" ::: "memory");
    __syncthreads();

    if (mma_warp) {
        const int mrow0 = (w & 3) * 16, ncol0 = (w >> 2) * 32;
        const int ar = mrow0 + (lane & 15), acl = lane >> 4, ar7 = ar & 7;
        const int br_off = (lane & 7) + ((lane & 16) >> 1), bcl = (lane >> 3) & 1;
        const int rg = lane >> 2, tg = lane & 3;
        const uint32_t abase = sb + (uint32_t)ar * 256u;
        const int cidx0 = (ncol0 >> 3) + bcl;
        const int cidx1 = cidx0 + 2;

        uint32_t auh[8][2][4];
        #pragma unroll
        for (int ks = 0; ks < 8; ++ks) {
            const uint32_t aa = abase + (uint32_t)(((ks * 2 + acl) ^ ar7) << 4);
            LDM4(auh[ks][0], aa);
            LDM4(auh[ks][1], aa + 32768);
        }

        uint32_t buf = 0;
        for (; widx < 1024; widx += 74) {
            const int chunk = widx >> 1, lh = widx & 1;
            const size_t cb = (size_t)chunk * 16384;

            float acc0[4][4], acc1[4][4];
            #pragma unroll
            for (int j = 0; j < 4; ++j)
                #pragma unroll
                for (int q = 0; q < 4; ++q) { acc0[j][q] = 0.f; acc1[j][q] = 0.f; }

            const uint32_t bbuf = sb + BH_OFF + buf * 65536u;
            #pragma unroll
            for (int ks = 0; ks < 8; ++ks) {
                uint32_t al0[4], al1[4];
                const uint32_t aa = abase + (uint32_t)(((ks * 2 + acl) ^ ar7) << 4);
                LDM4(al0, aa + 16384);
                LDM4(al1, aa + 49152);

                const int row = ks * 16 + br_off;
                const uint32_t rb = bbuf + (uint32_t)row * 128u;
                const int r7 = row & 7;
                {
                    uint32_t bf[4][4], nb2[4], nb3[4];
                    const uint32_t ba = rb + (uint32_t)((cidx0 ^ r7) << 4);
                    LDM4T(bf[0], ba);
                    LDM4T(bf[1], ba + 16384);
                    LDM4T(bf[2], ba + 32768);
                    LDM4T(bf[3], ba + 49152);
                    #pragma unroll
                    for (int q = 0; q < 4; ++q) { nb2[q] = bf[2][q] ^ SGN; nb3[q] = bf[3][q] ^ SGN; }
                    MMA12H(acc0[0], acc1[0], auh[ks][0], auh[ks][1], al0, al1, bf, nb2, nb3, 0)
                    MMA12H(acc0[1], acc1[1], auh[ks][0], auh[ks][1], al0, al1, bf, nb2, nb3, 1)
                }
                {
                    uint32_t bf[4][4], nb2[4], nb3[4];
                    const uint32_t ba = rb + (uint32_t)((cidx1 ^ r7) << 4);
                    LDM4T(bf[0], ba);
                    LDM4T(bf[1], ba + 16384);
                    LDM4T(bf[2], ba + 32768);
                    LDM4T(bf[3], ba + 49152);
                    #pragma unroll
                    for (int q = 0; q < 4; ++q) { nb2[q] = bf[2][q] ^ SGN; nb3[q] = bf[3][q] ^ SGN; }
                    MMA12H(acc0[2], acc1[2], auh[ks][0], auh[ks][1], al0, al1, bf, nb2, nb3, 0)
                    MMA12H(acc0[3], acc1[3], auh[ks][0], auh[ks][1], al0, al1, bf, nb2, nb3, 1)
                }
            }

            {
                const size_t row0 = (size_t)khalf * 64 + mrow0 + rg;
                float* o0 = out + cb;
                float* o1 = out + NSTATE + cb;
                #pragma unroll
                for (int g = 0; g < 2; ++g)
                    #pragma unroll
                    for (int j2 = 0; j2 < 2; ++j2) {
                        const int j = g * 2 + j2;
                        const int n = lh * 64 + ncol0 + g * 16 + j2 * 8 + tg * 2;
                        *(float2*)(o0 + row0 * 128 + n)       = make_float2(acc0[j][0], acc0[j][1]);
                        *(float2*)(o0 + (row0 + 8) * 128 + n) = make_float2(acc0[j][2], acc0[j][3]);
                        *(float2*)(o1 + row0 * 128 + n)       = make_float2(acc1[j][0], acc1[j][1]);
                        *(float2*)(o1 + (row0 + 8) * 128 + n) = make_float2(acc1[j][2], acc1[j][3]);
                    }
            }
            __syncthreads();
            buf ^= 1u;
        }
    } else {
        const int pt = t - 256;
        uint32_t buf = 0;
        for (; widx < 1024; widx += 74) {
            const int nwidx = widx + 74;
            if (nwidx < 1024) {
                const int nchunk = nwidx >> 1, nlh = nwidx & 1;
                const size_t ncb = (size_t)nchunk * 16384;
                #pragma unroll
                for (int s = 0; s < 16; ++s) {
                    const int slot = pt + 128 * s;
                    const int c = slot & 7, a = (slot >> 3) & 127, ch = slot >> 10;
                    const float4* p = (const float4*)(in + (size_t)ch * NSTATE + ncb + a * 128 + nlh * 64 + c * 8);
                    uint4 hi, lo;
                    cvt8(p[0], p[1], &hi, &lo);
                    char* wp = smem + BH_OFF + (buf ^ 1u) * 65536u + (ch * 2) * 16384 + a * 128
                             + ((c ^ (a & 7)) * 16);
                    *(uint4*)wp = hi;
                    *(uint4*)(wp + 16384) = lo;
                }
            }
            __syncthreads();
            buf ^= 1u;
        }
    }
}

// ---------------------------------------------------------------------------
extern "C" void kernel_launch(void* const* d_in, const int* in_sizes, int n_in,
                              void* d_out, int out_size)
{
    const float* state = (const float*)d_in[0];
    const float* U     = (const float*)d_in[1];
    if (n_in >= 2 && in_sizes[0] < in_sizes[1]) {
        const float* tmp = state; state = U; U = tmp;
    }
    float* out = (float*)d_out;

    float* scratch = nullptr;
    cudaGetSymbolAddress((void**)&scratch, g_scratch);
    __nv_bfloat16* ubf = nullptr;
    cudaGetSymbolAddress((void**)&ubf, g_ubf);

    cudaFuncSetAttribute(gate_lowg,  cudaFuncAttributeMaxDynamicSharedMemorySize, (int)SMEM_BYTES_LOG);
    cudaFuncSetAttribute(gate_highs, cudaFuncAttributeMaxDynamicSharedMemorySize, (int)SMEM_BYTES_HI);

    prep_u<<<256, 256>>>(U);
    gate_lowg<<<148, 384, SMEM_BYTES_LOG>>>(state,   scratch, ubf);            // gate 0
    gate_lowg<<<148, 384, SMEM_BYTES_LOG>>>(scratch, out,     ubf + 98304);    // gate 1
    gate_lowg<<<148, 384, SMEM_BYTES_LOG>>>(out,     scratch, ubf + 196608);   // gate 2
    gate_highs<<<148, 384, SMEM_BYTES_HI>>>(scratch, out,     ubf + 294912);   // gate 3
}